// round 10
// baseline (speedup 1.0000x reference)
#include <cuda_runtime.h>

#define BATCH 4
#define SEQ   4096
#define EMBED 768
#define HEAD  64
#define NQB   (SEQ / 64)

typedef unsigned long long u64;

// Scratch for projected Q, K, V  (3 x 4 MB). __device__ globals: no allocation.
__device__ float g_Q[BATCH * SEQ * HEAD];
__device__ float g_K[BATCH * SEQ * HEAD];
__device__ float g_V[BATCH * SEQ * HEAD];

// XOR-granule swizzle for [a][b] tiles with 64-float rows.
__device__ __forceinline__ int swz4(int a, int b4) {
    return a * 64 + ((((b4 >> 2) ^ (a >> 2)) & 15) << 2);
}
__device__ __forceinline__ int swz1(int a, int b) {
    return swz4(a, b & ~3) + (b & 3);
}

// ---- packed f32x2 helpers (SASS FFMA2 — only reachable via PTX) ----------
__device__ __forceinline__ void fma2(u64 &d, u64 a, u64 b) {
    asm("fma.rn.f32x2 %0, %1, %2, %0;" : "+l"(d) : "l"(a), "l"(b));
}
__device__ __forceinline__ void mul2(u64 &d, u64 a) {
    asm("mul.rn.f32x2 %0, %0, %1;" : "+l"(d) : "l"(a));
}
__device__ __forceinline__ u64 dup2(float a) {
    u64 r; asm("mov.b64 %0, {%1, %1};" : "=l"(r) : "f"(a)); return r;
}
__device__ __forceinline__ float2 unpk(u64 v) {
    float2 r; asm("mov.b64 {%0, %1}, %2;" : "=f"(r.x), "=f"(r.y) : "l"(v));
    return r;
}
__device__ __forceinline__ float ex2f(float x) {
    float r; asm("ex2.approx.ftz.f32 %0, %1;" : "=f"(r) : "f"(x)); return r;
}

// ---------------------------------------------------------------------------
// QKV projection (unchanged — measured near fp32 scalar peak, ~111us)
// ---------------------------------------------------------------------------
__global__ __launch_bounds__(256) void qkv_proj(
    const float* __restrict__ x,
    const float* __restrict__ Wq, const float* __restrict__ bq,
    const float* __restrict__ Wk, const float* __restrict__ bk,
    const float* __restrict__ Wv, const float* __restrict__ bv)
{
    __shared__ float As[32 * 64];
    __shared__ float Bs[32 * 64];

    const float* W; const float* bias; float* out;
    if (blockIdx.y == 0)      { W = Wq; bias = bq; out = g_Q; }
    else if (blockIdx.y == 1) { W = Wk; bias = bk; out = g_K; }
    else                      { W = Wv; bias = bv; out = g_V; }

    const int tid = threadIdx.x;
    const int ty = tid >> 4;
    const int tx = tid & 15;
    const int mBase = blockIdx.x * 64;

    float c[4][4] = {};

    for (int k0 = 0; k0 < EMBED; k0 += 32) {
        #pragma unroll
        for (int i = 0; i < 2; i++) {
            int f4 = tid + i * 256;
            int m  = f4 >> 3;
            int kq = (f4 & 7) << 2;
            float4 v = *(const float4*)&x[(size_t)(mBase + m) * EMBED + k0 + kq];
            As[swz1(kq + 0, m)] = v.x;
            As[swz1(kq + 1, m)] = v.y;
            As[swz1(kq + 2, m)] = v.z;
            As[swz1(kq + 3, m)] = v.w;
            int kk = f4 >> 4;
            int h  = (f4 & 15) << 2;
            *(float4*)&Bs[kk * 64 + h] = *(const float4*)&W[(size_t)(k0 + kk) * HEAD + h];
        }
        __syncthreads();

        #pragma unroll
        for (int kk = 0; kk < 32; kk++) {
            float4 a4 = *(const float4*)&As[swz4(kk, ty << 2)];
            float4 b4 = *(const float4*)&Bs[kk * 64 + (tx << 2)];
            float a[4] = {a4.x, a4.y, a4.z, a4.w};
            float b[4] = {b4.x, b4.y, b4.z, b4.w};
            #pragma unroll
            for (int r = 0; r < 4; r++)
                #pragma unroll
                for (int cc = 0; cc < 4; cc++)
                    c[r][cc] = fmaf(a[r], b[cc], c[r][cc]);
        }
        __syncthreads();
    }

    float4 bb = *(const float4*)&bias[tx << 2];
    float bv4[4] = {bb.x, bb.y, bb.z, bb.w};
    #pragma unroll
    for (int r = 0; r < 4; r++) {
        float4 o = make_float4(c[r][0] + bv4[0], c[r][1] + bv4[1],
                               c[r][2] + bv4[2], c[r][3] + bv4[3]);
        *(float4*)&out[(size_t)(mBase + (ty << 2) + r) * HEAD + (tx << 2)] = o;
    }
}

// ---------------------------------------------------------------------------
// Flash attention, causal. BLOCK = 64x64, 256 threads, 4x4 micro-tile,
// all FMAs as packed f32x2 (pairs over the column dim of each GEMM).
// smem (dynamic, 96 KB):
//   QsDup[64h][128]  Q rows duplicated: (q_r,q_r) pairs     (written once)
//   Ks   [64h][64j]  K transposed, swizzled                 (per iter)
//   Vs   [64j][64h]  V, swizzled                            (per iter)
//   PdT  [64j][128]  P rows duplicated, granule-swizzled    (per iter)
// K register-prefetched one iter ahead; V LDG issued at iter top,
// stored to smem after softmax -> global latency fully hidden.
// ---------------------------------------------------------------------------
__global__ __launch_bounds__(256) void attn(float* __restrict__ out)
{
    extern __shared__ float sm[];
    float* QsDup = sm;           // 8192 floats
    float* Ks    = sm + 8192;    // 4096
    float* Vs    = sm + 12288;   // 4096
    float* PdT   = sm + 16384;   // 8192

    const int b   = blockIdx.y;
    const int qb  = NQB - 1 - blockIdx.x;   // heavy blocks first
    const int tid = threadIdx.x;
    const int ty  = tid >> 4;               // 0..15 query micro-row group
    const int tx  = tid & 15;               // 0..15 key/head micro-col group
    const int lr  = tid >> 4;               // load row base
    const int lh  = (tid & 15) << 2;        // load col

    const float* Qg = g_Q + ((size_t)b * SEQ + (size_t)qb * 64) * HEAD;
    const float* Kg = g_K + (size_t)b * SEQ * HEAD;
    const float* Vg = g_V + (size_t)b * SEQ * HEAD;

    // ---- Q tile -> QsDup (duplicated pairs; one-time, conflicts amortized)
    #pragma unroll
    for (int i = 0; i < 4; i++) {
        int r = lr + i * 16;
        float4 v = *(const float4*)&Qg[(size_t)r * HEAD + lh];
        float vv[4] = {v.x, v.y, v.z, v.w};
        #pragma unroll
        for (int c = 0; c < 4; c++)
            *(float2*)&QsDup[(lh + c) * 128 + 2 * r] = make_float2(vv[c], vv[c]);
    }

    u64 acc2[4][2];
    float m_r[4], l_r[4];
    #pragma unroll
    for (int r = 0; r < 4; r++) {
        m_r[r] = -1e30f; l_r[r] = 0.0f;
        acc2[r][0] = 0ull; acc2[r][1] = 0ull;
    }

    // scale folded with log2(e): softmax done in exp2 domain
    const float SCALE2 = 0.125f * 1.44269504088896340736f;

    // prefetch K(0) into registers
    float4 kreg[4];
    #pragma unroll
    for (int i = 0; i < 4; i++)
        kreg[i] = *(const float4*)&Kg[(size_t)(lr + 16 * i) * HEAD + lh];

    for (int kb = 0; kb <= qb; kb++) {
        // issue V loads now; consumed (stored to smem) after softmax
        const float* Vt = Vg + (size_t)kb * 64 * HEAD;
        float4 vreg[4];
        #pragma unroll
        for (int i = 0; i < 4; i++)
            vreg[i] = *(const float4*)&Vt[(size_t)(lr + 16 * i) * HEAD + lh];

        __syncthreads();   // PV(kb-1) finished reading PdT/Vs; Ks free

        // store prefetched K transposed (swizzled)
        #pragma unroll
        for (int i = 0; i < 4; i++) {
            int r = lr + 16 * i;
            float kv[4] = {kreg[i].x, kreg[i].y, kreg[i].z, kreg[i].w};
            #pragma unroll
            for (int c = 0; c < 4; c++)
                Ks[swz1(lh + c, r)] = kv[c];
        }
        // prefetch next K tile (completes during QK/softmax)
        if (kb < qb) {
            const float* Kt = Kg + (size_t)(kb + 1) * 64 * HEAD;
            #pragma unroll
            for (int i = 0; i < 4; i++)
                kreg[i] = *(const float4*)&Kt[(size_t)(lr + 16 * i) * HEAD + lh];
        }
        __syncthreads();   // Ks ready (iter 0: QsDup ready too)

        // ---- S = Q K^T : packed over key columns --------------------------
        u64 s2[4][2];
        s2[0][0]=0ull; s2[0][1]=0ull; s2[1][0]=0ull; s2[1][1]=0ull;
        s2[2][0]=0ull; s2[2][1]=0ull; s2[3][0]=0ull; s2[3][1]=0ull;

        const float* qbase = QsDup + 8 * ty;
        #pragma unroll
        for (int kk = 0; kk < 64; kk++) {
            ulonglong2 qA = *(const ulonglong2*)(qbase + kk * 128);      // (q0,q0),(q1,q1)
            ulonglong2 qB = *(const ulonglong2*)(qbase + kk * 128 + 4);  // (q2,q2),(q3,q3)
            ulonglong2 kk2 = *(const ulonglong2*)&Ks[swz4(kk, tx << 2)]; // (k0,k1),(k2,k3)
            fma2(s2[0][0], qA.x, kk2.x); fma2(s2[0][1], qA.x, kk2.y);
            fma2(s2[1][0], qA.y, kk2.x); fma2(s2[1][1], qA.y, kk2.y);
            fma2(s2[2][0], qB.x, kk2.x); fma2(s2[2][1], qB.x, kk2.y);
            fma2(s2[3][0], qB.y, kk2.x); fma2(s2[3][1], qB.y, kk2.y);
        }

        // ---- online softmax (scalar) --------------------------------------
        float p[4][4];
        #pragma unroll
        for (int r = 0; r < 4; r++) {
            float2 v01 = unpk(s2[r][0]);
            float2 v23 = unpk(s2[r][1]);
            float sr[4] = {v01.x, v01.y, v23.x, v23.y};
            if (kb == qb) {
                int trow = (ty << 2) + r;
                #pragma unroll
                for (int cc = 0; cc < 4; cc++) {
                    int tcol = (tx << 2) + cc;
                    sr[cc] = (tcol <= trow) ? sr[cc] * SCALE2 : -1e30f;
                }
            } else {
                #pragma unroll
                for (int cc = 0; cc < 4; cc++) sr[cc] *= SCALE2;
            }
            float m0 = fmaxf(fmaxf(sr[0], sr[1]), fmaxf(sr[2], sr[3]));
            #pragma unroll
            for (int off = 8; off > 0; off >>= 1)
                m0 = fmaxf(m0, __shfl_xor_sync(0xffffffffu, m0, off));
            float newm  = fmaxf(m_r[r], m0);
            float alpha = ex2f(m_r[r] - newm);
            float lsum  = 0.0f;
            #pragma unroll
            for (int cc = 0; cc < 4; cc++) {
                float e = ex2f(sr[cc] - newm);
                p[r][cc] = e;
                lsum += e;
            }
            #pragma unroll
            for (int off = 8; off > 0; off >>= 1)
                lsum += __shfl_xor_sync(0xffffffffu, lsum, off);
            l_r[r] = l_r[r] * alpha + lsum;
            m_r[r] = newm;
            u64 al = dup2(alpha);
            mul2(acc2[r][0], al);
            mul2(acc2[r][1], al);
        }

        // ---- store P duplicated (granule-swizzled) + V tile ---------------
        #pragma unroll
        for (int cc = 0; cc < 4; cc++) {
            int j  = (tx << 2) + cc;
            int gs = (2 * ty) ^ (((j >> 2) & 15) << 1);
            *(float4*)&PdT[j * 128 + gs * 4] =
                make_float4(p[0][cc], p[0][cc], p[1][cc], p[1][cc]);
            *(float4*)&PdT[j * 128 + gs * 4 + 4] =
                make_float4(p[2][cc], p[2][cc], p[3][cc], p[3][cc]);
        }
        #pragma unroll
        for (int i = 0; i < 4; i++)
            *(float4*)&Vs[swz4(lr + 16 * i, lh)] = vreg[i];

        __syncthreads();   // PdT + Vs ready

        // ---- O += P V : packed over head columns --------------------------
        #pragma unroll
        for (int j = 0; j < 64; j++) {
            int gs = (2 * ty) ^ (((j >> 2) & 15) << 1);
            ulonglong2 pA = *(const ulonglong2*)&PdT[j * 128 + gs * 4];     // (p0,p0),(p1,p1)
            ulonglong2 pB = *(const ulonglong2*)&PdT[j * 128 + gs * 4 + 4]; // (p2,p2),(p3,p3)
            ulonglong2 vv = *(const ulonglong2*)&Vs[swz4(j, tx << 2)];      // (v0,v1),(v2,v3)
            fma2(acc2[0][0], pA.x, vv.x); fma2(acc2[0][1], pA.x, vv.y);
            fma2(acc2[1][0], pA.y, vv.x); fma2(acc2[1][1], pA.y, vv.y);
            fma2(acc2[2][0], pB.x, vv.x); fma2(acc2[2][1], pB.x, vv.y);
            fma2(acc2[3][0], pB.y, vv.x); fma2(acc2[3][1], pB.y, vv.y);
        }
    }

    // ---- epilogue: normalize and store ------------------------------------
    float* Og = out + ((size_t)b * SEQ + (size_t)qb * 64) * HEAD;
    #pragma unroll
    for (int r = 0; r < 4; r++) {
        float inv = 1.0f / l_r[r];
        float2 a01 = unpk(acc2[r][0]);
        float2 a23 = unpk(acc2[r][1]);
        float4 o = make_float4(a01.x * inv, a01.y * inv,
                               a23.x * inv, a23.y * inv);
        *(float4*)&Og[(size_t)((ty << 2) + r) * HEAD + (tx << 2)] = o;
    }
}

// ---------------------------------------------------------------------------
#define ATTN_SMEM (24576 * (int)sizeof(float))   // 96 KB dynamic

extern "C" void kernel_launch(void* const* d_in, const int* in_sizes, int n_in,
                              void* d_out, int out_size)
{
    const float* x  = (const float*)d_in[0];
    const float* Wq = (const float*)d_in[1];
    const float* bq = (const float*)d_in[2];
    const float* Wk = (const float*)d_in[3];
    const float* bk = (const float*)d_in[4];
    const float* Wv = (const float*)d_in[5];
    const float* bv = (const float*)d_in[6];
    float* out = (float*)d_out;

    cudaFuncSetAttribute(attn, cudaFuncAttributeMaxDynamicSharedMemorySize,
                         ATTN_SMEM);

    dim3 gp((BATCH * SEQ) / 64, 3);
    qkv_proj<<<gp, 256>>>(x, Wq, bq, Wk, bk, Wv, bv);

    dim3 ga(NQB, BATCH);
    attn<<<ga, 256, ATTN_SMEM>>>(out);
}